// round 5
// baseline (speedup 1.0000x reference)
#include <cuda_runtime.h>

typedef unsigned long long u64;

// Problem constants: N=2, C=2, H=W=D=64, R=3, WEIGHT=1, SIGMA_XY=6, SIGMA_IMG=0.1
static constexpr int H = 64, W = 64, D = 64, NN = 2;
static constexpr int NBLK = 2 * 64 * 8;   // n * i * jc = 1024 blocks of 64 threads

__device__ float g_partials[NBLK];
__device__ unsigned int g_count = 0;

__device__ __forceinline__ float ex2f(float x) {
    float y;
    asm("ex2.approx.ftz.f32 %0, %1;" : "=f"(y) : "f"(x));
    return y;
}
__device__ __forceinline__ u64 pk(float a, float b) {
    u64 r; asm("mov.b64 %0, {%1, %2};" : "=l"(r) : "f"(a), "f"(b)); return r;
}
__device__ __forceinline__ void upk(float& a, float& b, u64 v) {
    asm("mov.b64 {%0, %1}, %2;" : "=f"(a), "=f"(b) : "l"(v));
}
__device__ __forceinline__ u64 fma2(u64 a, u64 b, u64 c) {
    u64 r; asm("fma.rn.f32x2 %0, %1, %2, %3;" : "=l"(r) : "l"(a), "l"(b), "l"(c)); return r;
}
__device__ __forceinline__ u64 add2(u64 a, u64 b) {
    u64 r; asm("add.rn.f32x2 %0, %1, %2;" : "=l"(r) : "l"(a), "l"(b)); return r;
}
__device__ __forceinline__ u64 mul2(u64 a, u64 b) {
    u64 r; asm("mul.rn.f32x2 %0, %1, %2;" : "=l"(r) : "l"(a), "l"(b)); return r;
}

// KS = sqrt(50 * log2(e))
#define KS 8.4932180864f
#define HALFL2E 0.0200373478f  /* 0.5/36 * log2(e) */
#define NEGBIG -1.0e30f

__global__ __launch_bounds__(64) void crf_main(
    const float* __restrict__ yg, const float* __restrict__ sg,
    float* __restrict__ out)
{
    const int d4 = threadIdx.x;          // 0..7  -> float4 chunks d4 and d4+8
    const int ty = threadIdx.y;          // 0..7  -> j within 8-col chunk
    const int b  = blockIdx.x;
    const int jc = b & 7;
    const int i  = (b >> 3) & 63;
    const int n  = b >> 9;
    const int j  = jc * 8 + ty;

    const float4* __restrict__ s4 = (const float4*)sg;
    const float4* __restrict__ y4 = (const float4*)yg;

    // sample layout: ((n*H + i)*W + j)*D + d   -> float4 index
    const int bs = (n * H + i) * (W * 16) + j * 16 + d4;
    // y channel 0: (((n*2)*H + i)*W + j)*D + d
    const int by = (n * 2 * H + i) * (W * 16) + j * 16 + d4;

    const float4 sca = s4[bs],     scb = s4[bs + 8];
    const float4 yca = y4[by],     ycb = y4[by + 8];

    const u64 KS2  = pk(KS, KS);
    const u64 NKS2 = pk(-KS, -KS);

    // Four packed "halves": a01, a23, b01, b23  (8 d-values total)
    u64 na[4], pa[4];
    {
        const u64 s_[4] = { pk(sca.x, sca.y), pk(sca.z, sca.w),
                            pk(scb.x, scb.y), pk(scb.z, scb.w) };
        #pragma unroll
        for (int h = 0; h < 4; ++h) {
            na[h] = mul2(NKS2, s_[h]);   // -KS*sc
            pa[h] = mul2(KS2,  s_[h]);   // +KS*sc
        }
    }

    u64 S1[4] = {0ull, 0ull, 0ull, 0ull};   // sum of k
    u64 S2[4] = {0ull, 0ull, 0ull, 0ull};   // sum of k*yq

    // Unordered in-bounds pairs: positive offsets only, doubled at the end.
    // Branchless: OOB -> offset clamped to center, lw -> -1e30 => ex2 == 0.
    #pragma unroll
    for (int di = 0; di <= 3; ++di) {
        #pragma unroll
        for (int dj = -3; dj <= 3; ++dj) {
            if (di == 0 && dj <= 0) continue;
            const float lw = -(float)(di * di + dj * dj) * HALFL2E;
            const bool v = ((i + di) < H) & ((unsigned)(j + dj) < (unsigned)W);
            const int off = v ? (di * W + dj) * 16 : 0;
            const float lwv = v ? lw : NEGBIG;
            const u64 lw2 = pk(lwv, lwv);

            const float4 sqa = s4[bs + off], sqb = s4[bs + off + 8];
            const float4 yqa = y4[by + off], yqb = y4[by + off + 8];

            const u64 sq_[4] = { pk(sqa.x, sqa.y), pk(sqa.z, sqa.w),
                                 pk(sqb.x, sqb.y), pk(sqb.z, sqb.w) };
            const u64 yq_[4] = { pk(yqa.x, yqa.y), pk(yqa.z, yqa.w),
                                 pk(yqb.x, yqb.y), pk(yqb.z, yqb.w) };

            #pragma unroll
            for (int h = 0; h < 4; ++h) {
                const u64 t  = fma2(KS2,  sq_[h], na[h]);   //  KS*(sq - sc)
                const u64 nt = fma2(NKS2, sq_[h], pa[h]);   // -KS*(sq - sc)
                const u64 w  = fma2(t, nt, lw2);            //  lw - t^2
                float w0, w1; upk(w0, w1, w);
                const u64 k = pk(ex2f(w0), ex2f(w1));
                S1[h] = add2(S1[h], k);
                S2[h] = fma2(k, yq_[h], S2[h]);
            }
        }
    }

    // Epilogue: acc = sum_h sum_lane [ yp*S1 + (1-2*yp)*S2 ],  then *2 (directed)
    const float ypv[8] = { yca.x, yca.y, yca.z, yca.w, ycb.x, ycb.y, ycb.z, ycb.w };
    float acc = 0.0f;
    #pragma unroll
    for (int h = 0; h < 4; ++h) {
        float s1a, s1b, s2a, s2b;
        upk(s1a, s1b, S1[h]); upk(s2a, s2b, S2[h]);
        const float ya = ypv[2 * h], yb = ypv[2 * h + 1];
        acc += ya * s1a + fmaf(-2.0f * ya, s2a, s2a);
        acc += yb * s1b + fmaf(-2.0f * yb, s2b, s2b);
    }
    acc *= 2.0f;

    // Out-of-bounds slots: neighbor features zero-padded ->
    // k_oob = exp(-0.5*(fr^2+fc^2+fs^2)), identical for every OOB slot of a pixel.
    {
        const int ir = min(i + 3, H - 1) - max(i - 3, 0) + 1;
        const int ic = min(j + 3, W - 1) - max(j - 3, 0) + 1;
        const float cnt = (float)(49 - ir * ic);
        if (cnt > 0.0f) {
            const float cij = -(float)(i * i + j * j) * HALFL2E;
            float e = 0.0f;
            #pragma unroll
            for (int h = 0; h < 4; ++h) {
                float a0, a1; upk(a0, a1, na[h]);
                e += ex2f(fmaf(a0, -a0, cij)) + ex2f(fmaf(a1, -a1, cij));
            }
            acc = fmaf(cnt, e, acc);
        }
    }

    // ---- Block tree reduction (deterministic) ----
    __shared__ float red[64];
    __shared__ bool is_last;
    const int tid = ty * 8 + d4;
    red[tid] = acc;
    __syncthreads();
    #pragma unroll
    for (int offr = 32; offr > 0; offr >>= 1) {
        if (tid < offr) red[tid] += red[tid + offr];
        __syncthreads();
    }

    // ---- Last-block-done global reduction (fixed order => deterministic) ----
    if (tid == 0) {
        g_partials[b] = red[0];
        __threadfence();
        unsigned int v = atomicAdd(&g_count, 1u);
        is_last = (v == (unsigned)(NBLK - 1));
    }
    __syncthreads();

    if (is_last) {
        __threadfence();
        __shared__ double dred[64];
        double sum = 0.0;
        #pragma unroll
        for (int k = 0; k < NBLK / 64; ++k)
            sum += (double)g_partials[tid + k * 64];
        dred[tid] = sum;
        __syncthreads();
        #pragma unroll
        for (int offr = 32; offr > 0; offr >>= 1) {
            if (tid < offr) dred[tid] += dred[tid + offr];
            __syncthreads();
        }
        if (tid == 0) {
            out[0] = (float)(dred[0] / (double)(NN * D * H * W));
            g_count = 0;   // reset for next graph replay
        }
    }
}

extern "C" void kernel_launch(void* const* d_in, const int* in_sizes, int n_in,
                              void* d_out, int out_size)
{
    const float* y = (const float*)d_in[0];   // (2,2,64,64,64) softmax
    const float* s = (const float*)d_in[1];   // (2,1,64,64,64) sample
    if (n_in >= 2 && in_sizes[0] == 2 * 1 * H * W * D) {
        const float* tmp = y; y = s; s = tmp;
    }

    dim3 blk(8, 8);
    crf_main<<<NBLK, blk>>>(y, s, (float*)d_out);
}